// round 10
// baseline (speedup 1.0000x reference)
#include <cuda_runtime.h>
#include <cuda_fp16.h>
#include <cstdint>
#include <cstddef>

// ---------------------------------------------------------------------------
// out[B,O] = (x + sparse_pert) @ W + b
//          = x @ W + b + coeff * u[r] * W[idx[r], :]   (u = bitflip(g) - g)
// B=4096, F=16384, O=256, fp32.
//
// R10: R9 ncu showed tensor=36.4%, occ=12.5% -> latency-bound, NOT
// MMA-issue-bound. Fix: 512 threads/CTA (16 warps, 4x4 grid, 32x64 warp
// tile) -> 4 warps/SMSP, occ 25%. Same MMA volume, 2x latency hiding.
// ---------------------------------------------------------------------------

namespace {
constexpr int Bm = 4096;
constexpr int Fk = 16384;
constexpr int On = 256;

constexpr int BM = 128;
constexpr int BK = 32;
constexpr int SPLITK = 4;
constexpr int K_PER_CTA = Fk / SPLITK;     // 4096
constexpr int NT = K_PER_CTA / BK;         // 128 stages
constexpr int STAGES = 5;
constexpr int NTHREADS = 512;

// SMEM layout (bytes)
constexpr int RAWA_STAGE = BM * BK * 4;            // 16384 (fp32 x tile)
constexpr int BROW_PITCH = 80;                     // 64B data + 16B pad
constexpr int B_STAGE = 256 * BROW_PITCH;          // 20480
constexpr int ACONV = BM * BROW_PITCH;             // 10240

constexpr int OFF_RAWA = 0;
constexpr int OFF_B    = OFF_RAWA + STAGES * RAWA_STAGE;           // 81920
constexpr int OFF_AC   = OFF_B + STAGES * B_STAGE;                 // 184320
constexpr int SMEM_TOTAL = OFF_AC + ACONV;                         // 194560
}  // namespace

// Pre-transposed W: Wt[n, k] fp16 (8 MB). Static scratch.
__device__ __align__(16) __half g_Wt[(size_t)On * Fk];

// ---------------------------- helpers --------------------------------------
__device__ __forceinline__ uint32_t smem_u32(const void* p) {
    uint32_t a;
    asm("{ .reg .u64 t; cvta.to.shared.u64 t, %1; cvt.u32.u64 %0, t; }"
        : "=r"(a) : "l"(p));
    return a;
}

__device__ __forceinline__ void cp_async16(void* dst, const void* src) {
    asm volatile("cp.async.cg.shared.global [%0], [%1], 16;"
                 :: "r"(smem_u32(dst)), "l"(src) : "memory");
}
__device__ __forceinline__ void cp_commit() {
    asm volatile("cp.async.commit_group;" ::: "memory");
}
template <int N>
__device__ __forceinline__ void cp_wait() {
    asm volatile("cp.async.wait_group %0;" :: "n"(N) : "memory");
}

// pack f16(x1):f16(x0), x0 in low half
__device__ __forceinline__ uint32_t cvt_f16x2(float x1, float x0) {
    uint32_t d;
    asm("cvt.rn.f16x2.f32 %0, %1, %2;" : "=r"(d) : "f"(x1), "f"(x0));
    return d;
}

__device__ __forceinline__ void ldsm_x4(uint32_t r[4], uint32_t addr) {
    asm volatile(
        "ldmatrix.sync.aligned.m8n8.x4.shared.b16 {%0,%1,%2,%3}, [%4];"
        : "=r"(r[0]), "=r"(r[1]), "=r"(r[2]), "=r"(r[3]) : "r"(addr));
}

__device__ __forceinline__ void mma_f16(float c[4], const uint32_t a[4],
                                        const uint32_t b[2]) {
    asm volatile(
        "mma.sync.aligned.m16n8k16.row.col.f32.f16.f16.f32 "
        "{%0,%1,%2,%3},{%4,%5,%6,%7},{%8,%9},{%0,%1,%2,%3};"
        : "+f"(c[0]), "+f"(c[1]), "+f"(c[2]), "+f"(c[3])
        : "r"(a[0]), "r"(a[1]), "r"(a[2]), "r"(a[3]), "r"(b[0]), "r"(b[1]));
}

// ------------------- kernel 1: W transpose to fp16 -------------------------
__global__ void prep_w_kernel(const float* __restrict__ W) {
    __shared__ float t[32][33];
    int n0 = blockIdx.x * 32;
    int k0 = blockIdx.y * 32;
    int tx = threadIdx.x, ty = threadIdx.y;
#pragma unroll
    for (int j = 0; j < 4; j++) {
        int k = k0 + ty + j * 8;
        t[ty + j * 8][tx] = W[(size_t)k * On + n0 + tx];
    }
    __syncthreads();
#pragma unroll
    for (int j = 0; j < 4; j++) {
        int n = n0 + ty + j * 8;
        float v = t[tx][ty + j * 8];
        g_Wt[(size_t)n * Fk + k0 + tx] = __float2half_rn(v);
    }
}

// ------------ kernel 2: fused init + split-K fp16 mma.sync GEMM ------------
__global__ void __launch_bounds__(NTHREADS, 1)
gemm_kernel(const float* __restrict__ x, const float* __restrict__ W,
            const float* __restrict__ b, const float* __restrict__ coeff,
            const int* __restrict__ idx, const int* __restrict__ bitpos,
            float* __restrict__ out) {
    extern __shared__ char smem[];
    __shared__ float us[32];
    char* rawA = smem + OFF_RAWA;
    char* BS   = smem + OFF_B;
    char* Ac   = smem + OFF_AC;

    const int tid = threadIdx.x;
    const int lane = tid & 31, w = tid >> 5;
    const int wm = w & 3, wn = w >> 2;       // warp grid 4(M) x 4(N), 32x64 tile
    const int g = lane >> 2, q = lane & 3;

    const int m0 = blockIdx.x * BM;
    const int z  = blockIdx.z;
    const int kbase = z * K_PER_CTA;

    // ---- fused init: rows [m0+32z, m0+32z+32) of out = b + coeff*u*W[idx]
    // Safe: grid=128 CTAs <= 148 SMs at occ 1 -> single wave; inits complete
    // ~1us after launch, first epilogue atomic lands far later.
    {
        int r0 = m0 + z * 32;
        if (tid < 32) {
            int r = r0 + tid;
            int j = idx[r];
            float gg = x[(size_t)r * Fk + j];
            int gi = __float_as_int(gg) ^ (1 << bitpos[r]);
            us[tid] = (__int_as_float(gi) - gg) * coeff[0];
        }
        __syncthreads();
#pragma unroll
        for (int i = 0; i < 16; i++) {
            int e = tid + i * NTHREADS;
            int rr = e >> 8, c = e & 255;
            int r = r0 + rr;
            out[(size_t)r * On + c] =
                b[c] + us[rr] * W[(size_t)idx[r] * On + c];
        }
    }

    // ldmatrix per-lane address components (row within 16, k-16B half)
    const int lrow = lane & 15;
    const int lk16 = (lane >> 4) * 16;

    float acc[2][8][4];
#pragma unroll
    for (int i = 0; i < 2; i++)
#pragma unroll
        for (int j = 0; j < 8; j++)
#pragma unroll
            for (int r = 0; r < 4; r++) acc[i][j][r] = 0.0f;

    // ---- stage loader (always commits one group) ----
    auto issue = [&](int kt, int slot) {
        if (kt < NT) {
            const float* xg = x + (size_t)m0 * Fk + kbase + kt * BK;
            char* ra = rawA + slot * RAWA_STAGE;
#pragma unroll
            for (int i = 0; i < 2; i++) {
                int ch = tid + i * NTHREADS;      // 0..1023
                int row = ch >> 3, sub = ch & 7;
                int phys = sub ^ (row & 7);       // XOR swizzle (bank-free reads)
                cp_async16(ra + row * 128 + phys * 16,
                           xg + (size_t)row * Fk + sub * 4);
            }
            const __half* wt = g_Wt + kbase + kt * BK;
            char* bs = BS + slot * B_STAGE;
#pragma unroll
            for (int i = 0; i < 2; i++) {
                int ch = tid + i * NTHREADS;      // 0..1023
                int row = ch >> 2, sub = ch & 3;  // row 0..255
                cp_async16(bs + row * BROW_PITCH + sub * 16,
                           wt + (size_t)row * Fk + sub * 8);
            }
        }
        cp_commit();
    };

    issue(0, 0); issue(1, 1); issue(2, 2); issue(3, 3);

    // convert-thread mapping: quarter-row (8 floats) per thread
    const int crow = tid & 127;             // 0..127
    const int cq   = tid >> 7;              // 0..3 quarter of the 32-float row

    int slot = 0;       // slot of stage kt
    int pslot = 4;      // slot for prefetch stage kt+4
    for (int kt = 0; kt < NT; kt++) {
        cp_wait<3>();            // groups: 4+kt committed; group kt complete
        __syncthreads();         // data visible; mma of kt-1 done (slot reuse)

        issue(kt + 4, pslot);
        if (++pslot == STAGES) pslot = 0;

        // ---- convert raw x fp32 -> fp16 in SMEM (each elem once) ----
        {
            const char* ra = rawA + slot * RAWA_STAGE;
            uint32_t pk[4];
#pragma unroll
            for (int i = 0; i < 2; i++) {
                int phys = (cq * 2 + i) ^ (crow & 7);
                float4 v = *(const float4*)(ra + crow * 128 + phys * 16);
                pk[i * 2]     = cvt_f16x2(v.y, v.x);
                pk[i * 2 + 1] = cvt_f16x2(v.w, v.z);
            }
            *(uint4*)(Ac + crow * BROW_PITCH + cq * 16) =
                make_uint4(pk[0], pk[1], pk[2], pk[3]);
        }
        __syncthreads();

        // ---- MMA: 2 x k16, ldmatrix fragment loads ----
        const uint32_t aBase = smem_u32(Ac) +
            (wm * 32 + lrow) * BROW_PITCH + lk16;
        const uint32_t bBase = smem_u32(BS) + slot * B_STAGE +
            (wn * 64 + lrow) * BROW_PITCH + lk16;
#pragma unroll
        for (int kk = 0; kk < 2; kk++) {
            uint32_t af[2][4];
#pragma unroll
            for (int mt = 0; mt < 2; mt++)
                ldsm_x4(af[mt], aBase + mt * 16 * BROW_PITCH + kk * 32);
            uint32_t bf[8][2];
#pragma unroll
            for (int p = 0; p < 4; p++) {
                uint32_t r[4];
                ldsm_x4(r, bBase + p * 16 * BROW_PITCH + kk * 32);
                bf[2 * p][0] = r[0]; bf[2 * p + 1][0] = r[1];
                bf[2 * p][1] = r[2]; bf[2 * p + 1][1] = r[3];
            }
#pragma unroll
            for (int mt = 0; mt < 2; mt++)
#pragma unroll
                for (int nt = 0; nt < 8; nt++)
                    mma_f16(acc[mt][nt], af[mt], bf[nt]);
        }

        if (++slot == STAGES) slot = 0;
    }

    cp_wait<0>();  // drain outstanding cp.async before exit

    // ---- epilogue: atomicAdd into initialized out ----
#pragma unroll
    for (int mt = 0; mt < 2; mt++) {
        int r0 = m0 + wm * 32 + mt * 16 + g;
#pragma unroll
        for (int nt = 0; nt < 8; nt++) {
            int col = wn * 64 + nt * 8 + q * 2;
            float* p0 = out + (size_t)r0 * On + col;
            float* p1 = out + (size_t)(r0 + 8) * On + col;
            atomicAdd(p0,     acc[mt][nt][0]);
            atomicAdd(p0 + 1, acc[mt][nt][1]);
            atomicAdd(p1,     acc[mt][nt][2]);
            atomicAdd(p1 + 1, acc[mt][nt][3]);
        }
    }
}

// ---------------------------------------------------------------------------
extern "C" void kernel_launch(void* const* d_in, const int* in_sizes, int n_in,
                              void* d_out, int out_size) {
    const float* x      = (const float*)d_in[0];
    const float* W      = (const float*)d_in[1];
    const float* b      = (const float*)d_in[2];
    const float* coeff  = (const float*)d_in[3];
    const int*   idx    = (const int*)d_in[4];
    const int*   bitpos = (const int*)d_in[5];
    float* out = (float*)d_out;

    cudaFuncSetAttribute(gemm_kernel,
                         cudaFuncAttributeMaxDynamicSharedMemorySize,
                         SMEM_TOTAL);

    // 1) W -> transposed fp16 scratch
    prep_w_kernel<<<dim3(On / 32, Fk / 32), dim3(32, 8)>>>(W);
    // 2) fused init (rank-1 correction + bias) + split-K GEMM
    gemm_kernel<<<dim3(Bm / BM, 1, SPLITK), NTHREADS, SMEM_TOTAL>>>(
        x, W, b, coeff, idx, bitpos, out);
}

// round 11
// speedup vs baseline: 1.0152x; 1.0152x over previous
#include <cuda_runtime.h>
#include <cuda_fp16.h>
#include <cstdint>
#include <cstddef>

// ---------------------------------------------------------------------------
// out[B,O] = (x + sparse_pert) @ W + b
//          = x @ W + b + coeff * u[r] * W[idx[r], :]   (u = bitflip(g) - g)
// B=4096, F=16384, O=256, fp32.
//
// R11: HMMA m16n8k16 fallback cap measured at ~16cyc/SMSP (R9 vs R10:
// occupancy 12.5%->25% changed nothing). Floor = 142us gemm. This round
// removes the ~182cyc/stage overhead: software-pipelined convert (stage
// kt+1's fp32->fp16 convert overlaps stage kt's MMAs), ONE barrier/stage,
// double-buffered Ac, 5-slot rawA/B rings.
// ---------------------------------------------------------------------------

namespace {
constexpr int Bm = 4096;
constexpr int Fk = 16384;
constexpr int On = 256;

constexpr int BM = 128;
constexpr int BK = 32;
constexpr int SPLITK = 4;
constexpr int K_PER_CTA = Fk / SPLITK;     // 4096
constexpr int NT = K_PER_CTA / BK;         // 128 stages
constexpr int STAGES = 5;
constexpr int NTHREADS = 256;

// SMEM layout (bytes)
constexpr int RAWA_STAGE = BM * BK * 4;            // 16384 (fp32 x tile)
constexpr int BROW_PITCH = 80;                     // 64B data + 16B pad
constexpr int B_STAGE = 256 * BROW_PITCH;          // 20480
constexpr int ACONV = BM * BROW_PITCH;             // 10240 (x2 parity buffers)

constexpr int OFF_RAWA = 0;                                        // 81920
constexpr int OFF_B    = OFF_RAWA + STAGES * RAWA_STAGE;           // 81920
constexpr int OFF_AC   = OFF_B + STAGES * B_STAGE;                 // 184320
constexpr int SMEM_TOTAL = OFF_AC + 2 * ACONV;                     // 204800
}  // namespace

// Pre-transposed W: Wt[n, k] fp16 (8 MB). Static scratch.
__device__ __align__(16) __half g_Wt[(size_t)On * Fk];

// ---------------------------- helpers --------------------------------------
__device__ __forceinline__ uint32_t smem_u32(const void* p) {
    uint32_t a;
    asm("{ .reg .u64 t; cvta.to.shared.u64 t, %1; cvt.u32.u64 %0, t; }"
        : "=r"(a) : "l"(p));
    return a;
}

__device__ __forceinline__ void cp_async16(void* dst, const void* src) {
    asm volatile("cp.async.cg.shared.global [%0], [%1], 16;"
                 :: "r"(smem_u32(dst)), "l"(src) : "memory");
}
__device__ __forceinline__ void cp_commit() {
    asm volatile("cp.async.commit_group;" ::: "memory");
}
template <int N>
__device__ __forceinline__ void cp_wait() {
    asm volatile("cp.async.wait_group %0;" :: "n"(N) : "memory");
}

// pack f16(x1):f16(x0), x0 in low half
__device__ __forceinline__ uint32_t cvt_f16x2(float x1, float x0) {
    uint32_t d;
    asm("cvt.rn.f16x2.f32 %0, %1, %2;" : "=r"(d) : "f"(x1), "f"(x0));
    return d;
}

__device__ __forceinline__ void ldsm_x4(uint32_t r[4], uint32_t addr) {
    asm volatile(
        "ldmatrix.sync.aligned.m8n8.x4.shared.b16 {%0,%1,%2,%3}, [%4];"
        : "=r"(r[0]), "=r"(r[1]), "=r"(r[2]), "=r"(r[3]) : "r"(addr));
}

__device__ __forceinline__ void mma_f16(float c[4], const uint32_t a[4],
                                        const uint32_t b[2]) {
    asm volatile(
        "mma.sync.aligned.m16n8k16.row.col.f32.f16.f16.f32 "
        "{%0,%1,%2,%3},{%4,%5,%6,%7},{%8,%9},{%0,%1,%2,%3};"
        : "+f"(c[0]), "+f"(c[1]), "+f"(c[2]), "+f"(c[3])
        : "r"(a[0]), "r"(a[1]), "r"(a[2]), "r"(a[3]), "r"(b[0]), "r"(b[1]));
}

// ------------------- kernel 1: W transpose to fp16 -------------------------
__global__ void prep_w_kernel(const float* __restrict__ W) {
    __shared__ float t[32][33];
    int n0 = blockIdx.x * 32;
    int k0 = blockIdx.y * 32;
    int tx = threadIdx.x, ty = threadIdx.y;
#pragma unroll
    for (int j = 0; j < 4; j++) {
        int k = k0 + ty + j * 8;
        t[ty + j * 8][tx] = W[(size_t)k * On + n0 + tx];
    }
    __syncthreads();
#pragma unroll
    for (int j = 0; j < 4; j++) {
        int n = n0 + ty + j * 8;
        float v = t[tx][ty + j * 8];
        g_Wt[(size_t)n * Fk + k0 + tx] = __float2half_rn(v);
    }
}

// ------------ kernel 2: fused init + split-K fp16 mma.sync GEMM ------------
__global__ void __launch_bounds__(NTHREADS, 1)
gemm_kernel(const float* __restrict__ x, const float* __restrict__ W,
            const float* __restrict__ b, const float* __restrict__ coeff,
            const int* __restrict__ idx, const int* __restrict__ bitpos,
            float* __restrict__ out) {
    extern __shared__ char smem[];
    __shared__ float us[32];
    char* rawA = smem + OFF_RAWA;
    char* BS   = smem + OFF_B;
    char* Ac   = smem + OFF_AC;   // 2 parity buffers of ACONV bytes

    const int tid = threadIdx.x;
    const int lane = tid & 31, w = tid >> 5;
    const int wm = w & 1, wn = w >> 1;       // warp grid 2(M) x 4(N), 64x64 tile
    const int g = lane >> 2, q = lane & 3;

    const int m0 = blockIdx.x * BM;
    const int z  = blockIdx.z;
    const int kbase = z * K_PER_CTA;

    // ---- fused init: rows [m0+32z, m0+32z+32) of out = b + coeff*u*W[idx]
    // Safe: grid=128 CTAs <= 148 SMs at occ 1 -> single wave; inits complete
    // ~1us after launch, first epilogue atomic lands far later.
    {
        int r0 = m0 + z * 32;
        if (tid < 32) {
            int r = r0 + tid;
            int j = idx[r];
            float gg = x[(size_t)r * Fk + j];
            int gi = __float_as_int(gg) ^ (1 << bitpos[r]);
            us[tid] = (__int_as_float(gi) - gg) * coeff[0];
        }
        __syncthreads();
#pragma unroll
        for (int i = 0; i < 32; i++) {
            int e = tid + i * NTHREADS;
            int rr = e >> 8, c = e & 255;
            int r = r0 + rr;
            out[(size_t)r * On + c] =
                b[c] + us[rr] * W[(size_t)idx[r] * On + c];
        }
    }

    // ldmatrix per-lane address components (row within 16, k-16B half)
    const int lrow = lane & 15;
    const int lk16 = (lane >> 4) * 16;

    float acc[4][8][4];
#pragma unroll
    for (int i = 0; i < 4; i++)
#pragma unroll
        for (int j = 0; j < 8; j++)
#pragma unroll
            for (int r = 0; r < 4; r++) acc[i][j][r] = 0.0f;

    // ---- stage loader (always commits one group) ----
    auto issue = [&](int kt, int slot) {
        if (kt < NT) {
            const float* xg = x + (size_t)m0 * Fk + kbase + kt * BK;
            char* ra = rawA + slot * RAWA_STAGE;
#pragma unroll
            for (int i = 0; i < 4; i++) {
                int ch = tid + i * NTHREADS;      // 0..1023
                int row = ch >> 3, sub = ch & 7;
                int phys = sub ^ (row & 7);       // XOR swizzle (bank-free reads)
                cp_async16(ra + row * 128 + phys * 16,
                           xg + (size_t)row * Fk + sub * 4);
            }
            const __half* wt = g_Wt + kbase + kt * BK;
            char* bs = BS + slot * B_STAGE;
#pragma unroll
            for (int i = 0; i < 4; i++) {
                int ch = tid + i * NTHREADS;      // 0..1023
                int row = ch >> 2, sub = ch & 3;  // row 0..255
                cp_async16(bs + row * BROW_PITCH + sub * 16,
                           wt + (size_t)row * Fk + sub * 8);
            }
        }
        cp_commit();
    };

    // convert-thread mapping: conflict-free LDS.128 + STS.128 (half-row/thr)
    const int crow = (w & 3) * 32 + lane;   // 0..127
    const int chh  = w >> 2;                // half of the 32-float row

    auto convert = [&](int k) {             // rawA slot k%5 -> Ac[k&1]
        const char* ra = rawA + (k % STAGES) * RAWA_STAGE;
        char* dst = Ac + (k & 1) * ACONV;
        uint32_t pk[8];
#pragma unroll
        for (int i = 0; i < 4; i++) {
            int phys = (chh * 4 + i) ^ (crow & 7);
            float4 v = *(const float4*)(ra + crow * 128 + phys * 16);
            pk[i * 2]     = cvt_f16x2(v.y, v.x);
            pk[i * 2 + 1] = cvt_f16x2(v.w, v.z);
        }
        uint4* d = (uint4*)(dst + crow * BROW_PITCH + chh * 32);
        d[0] = make_uint4(pk[0], pk[1], pk[2], pk[3]);
        d[1] = make_uint4(pk[4], pk[5], pk[6], pk[7]);
    };

    // ---- prologue: 4 groups in flight, convert stage 0 ----
    issue(0, 0); issue(1, 1); issue(2, 2); issue(3, 3);
    cp_wait<3>();            // group 0 complete
    __syncthreads();         // visible to all
    convert(0);              // Ac[0] <- stage 0

    // ---- mainloop: ONE barrier per stage; convert(kt+1) overlaps MMA(kt) --
    int pslot = 4;           // slot for prefetch stage kt+4
    for (int kt = 0; kt < NT; kt++) {
        cp_wait<2>();        // committed 4+kt; group kt+1 complete
        __syncthreads();     // loads visible; prev MMA+convert done (reuse)

        issue(kt + 4, pslot);
        if (++pslot == STAGES) pslot = 0;

        // MMA on stage kt (Ac[kt&1], BS slot kt%5)
        const uint32_t aBase = smem_u32(Ac) + (kt & 1) * ACONV +
            (wm * 64 + lrow) * BROW_PITCH + lk16;
        const uint32_t bBase = smem_u32(BS) + (kt % STAGES) * B_STAGE +
            (wn * 64 + lrow) * BROW_PITCH + lk16;
#pragma unroll
        for (int kk = 0; kk < 2; kk++) {
            uint32_t af[4][4];
#pragma unroll
            for (int mt = 0; mt < 4; mt++)
                ldsm_x4(af[mt], aBase + mt * 16 * BROW_PITCH + kk * 32);
            uint32_t bf[8][2];
#pragma unroll
            for (int p = 0; p < 4; p++) {
                uint32_t r[4];
                ldsm_x4(r, bBase + p * 16 * BROW_PITCH + kk * 32);
                bf[2 * p][0] = r[0]; bf[2 * p + 1][0] = r[1];
                bf[2 * p][1] = r[2]; bf[2 * p + 1][1] = r[3];
            }
#pragma unroll
            for (int mt = 0; mt < 4; mt++)
#pragma unroll
                for (int nt = 0; nt < 8; nt++)
                    mma_f16(acc[mt][nt], af[mt], bf[nt]);
        }

        // convert NEXT stage's A while this stage's MMAs drain
        if (kt + 1 < NT) convert(kt + 1);
    }

    cp_wait<0>();  // drain outstanding cp.async before exit

    // ---- epilogue: atomicAdd into initialized out ----
#pragma unroll
    for (int mt = 0; mt < 4; mt++) {
        int r0 = m0 + wm * 64 + mt * 16 + g;
#pragma unroll
        for (int nt = 0; nt < 8; nt++) {
            int col = wn * 64 + nt * 8 + q * 2;
            float* p0 = out + (size_t)r0 * On + col;
            float* p1 = out + (size_t)(r0 + 8) * On + col;
            atomicAdd(p0,     acc[mt][nt][0]);
            atomicAdd(p0 + 1, acc[mt][nt][1]);
            atomicAdd(p1,     acc[mt][nt][2]);
            atomicAdd(p1 + 1, acc[mt][nt][3]);
        }
    }
}

// ---------------------------------------------------------------------------
extern "C" void kernel_launch(void* const* d_in, const int* in_sizes, int n_in,
                              void* d_out, int out_size) {
    const float* x      = (const float*)d_in[0];
    const float* W      = (const float*)d_in[1];
    const float* b      = (const float*)d_in[2];
    const float* coeff  = (const float*)d_in[3];
    const int*   idx    = (const int*)d_in[4];
    const int*   bitpos = (const int*)d_in[5];
    float* out = (float*)d_out;

    cudaFuncSetAttribute(gemm_kernel,
                         cudaFuncAttributeMaxDynamicSharedMemorySize,
                         SMEM_TOTAL);

    // 1) W -> transposed fp16 scratch
    prep_w_kernel<<<dim3(On / 32, Fk / 32), dim3(32, 8)>>>(W);
    // 2) fused init (rank-1 correction + bias) + split-K GEMM
    gemm_kernel<<<dim3(Bm / BM, 1, SPLITK), NTHREADS, SMEM_TOTAL>>>(
        x, W, b, coeff, idx, bitpos, out);
}